// round 3
// baseline (speedup 1.0000x reference)
#include <cuda_runtime.h>

// L1Loss: out = mean(|yhat - y|) over 64*128*4096 fp32 elements.
// R3: single kernel via last-block reduction (no zero-init kernel),
// single-wave grid (148 SMs x 8 CTAs at 256thr/32reg).

#define NBLOCKS 1184
#define NTHREADS 256

__device__ float g_partials[NBLOCKS];
__device__ unsigned int g_ticket = 0;   // self-resetting via atomicInc wrap

__global__ void __launch_bounds__(NTHREADS) l1_reduce_kernel(
    const float4* __restrict__ a,
    const float4* __restrict__ b,
    float* __restrict__ out,
    int n4,            // number of float4 elements
    int n_tail,        // scalar elements after n4*4
    float inv_n)
{
    float acc0 = 0.0f, acc1 = 0.0f;

    const int idx    = blockIdx.x * blockDim.x + threadIdx.x;
    const int stride = gridDim.x * blockDim.x;

    int i = idx;
    for (; i + stride < n4; i += 2 * stride) {
        float4 a0 = a[i];
        float4 a1 = a[i + stride];
        float4 b0 = b[i];
        float4 b1 = b[i + stride];
        acc0 += fabsf(a0.x - b0.x) + fabsf(a0.y - b0.y)
              + fabsf(a0.z - b0.z) + fabsf(a0.w - b0.w);
        acc1 += fabsf(a1.x - b1.x) + fabsf(a1.y - b1.y)
              + fabsf(a1.z - b1.z) + fabsf(a1.w - b1.w);
    }
    for (; i < n4; i += stride) {
        float4 x = a[i];
        float4 y = b[i];
        acc0 += fabsf(x.x - y.x) + fabsf(x.y - y.y)
              + fabsf(x.z - y.z) + fabsf(x.w - y.w);
    }

    // Scalar tail (N not divisible by 4)
    if (blockIdx.x == 0 && threadIdx.x < n_tail) {
        const float* af = (const float*)a;
        const float* bf = (const float*)b;
        int t = n4 * 4 + threadIdx.x;
        acc0 += fabsf(af[t] - bf[t]);
    }

    float acc = acc0 + acc1;

    // Intra-block reduction
    #pragma unroll
    for (int o = 16; o > 0; o >>= 1)
        acc += __shfl_down_sync(0xffffffffu, acc, o);

    __shared__ float smem[NTHREADS / 32];
    int lane = threadIdx.x & 31;
    int wid  = threadIdx.x >> 5;
    if (lane == 0) smem[wid] = acc;
    __syncthreads();

    __shared__ bool is_last;
    if (threadIdx.x == 0) {
        float v = 0.0f;
        #pragma unroll
        for (int w = 0; w < NTHREADS / 32; w++) v += smem[w];
        g_partials[blockIdx.x] = v;
        __threadfence();
        unsigned int t = atomicInc(&g_ticket, gridDim.x - 1);
        is_last = (t == gridDim.x - 1);
    }
    __syncthreads();

    // Last block to finish sums all partials and writes the result.
    if (is_last) {
        float v = 0.0f;
        for (int j = threadIdx.x; j < NBLOCKS; j += NTHREADS)
            v += g_partials[j];
        #pragma unroll
        for (int o = 16; o > 0; o >>= 1)
            v += __shfl_down_sync(0xffffffffu, v, o);
        if (lane == 0) smem[wid] = v;
        __syncthreads();
        if (threadIdx.x == 0) {
            float total = 0.0f;
            #pragma unroll
            for (int w = 0; w < NTHREADS / 32; w++) total += smem[w];
            out[0] = total * inv_n;
        }
    }
}

extern "C" void kernel_launch(void* const* d_in, const int* in_sizes, int n_in,
                              void* d_out, int out_size)
{
    const float* yhat = (const float*)d_in[0];
    const float* y    = (const float*)d_in[1];
    float* out = (float*)d_out;

    long long n = in_sizes[0];
    int n4 = (int)(n / 4);
    int n_tail = (int)(n - (long long)n4 * 4);
    float inv_n = 1.0f / (float)n;

    l1_reduce_kernel<<<NBLOCKS, NTHREADS>>>(
        (const float4*)yhat, (const float4*)y, out, n4, n_tail, inv_n);
}